// round 9
// baseline (speedup 1.0000x reference)
#include <cuda_runtime.h>
#include <cstdint>
#include <cstddef>

#define T_STEPS 2048
#define B_SIZE  256
#define I_SIZE  64
#define H_SIZE  128

// Scratch: precomputed input projections x@Wi + bi, layout [T][B][3*H]
__device__ float g_xproj[(size_t)T_STEPS * B_SIZE * 3 * H_SIZE];

__device__ __forceinline__ float sigmoidf_(float x) {
    return 1.0f / (1.0f + __expf(-x));
}
__device__ __forceinline__ float tanhf_(float x) {
    return 1.0f - 2.0f / (1.0f + __expf(2.0f * x));
}

// ---- packed f32x2 helpers (Blackwell FFMA2) --------------------------------
__device__ __forceinline__ unsigned long long fma2_(unsigned long long a,
                                                    unsigned long long b,
                                                    unsigned long long c) {
    unsigned long long d;
    asm("fma.rn.f32x2 %0, %1, %2, %3;" : "=l"(d) : "l"(a), "l"(b), "l"(c));
    return d;
}
__device__ __forceinline__ unsigned long long dup2_(float x) {
    unsigned long long d;
    asm("mov.b64 %0, {%1, %1};" : "=l"(d) : "f"(x));
    return d;
}
__device__ __forceinline__ unsigned long long pack2_(float a, float b) {
    unsigned long long d;
    asm("mov.b64 %0, {%1, %2};" : "=l"(d) : "f"(a), "f"(b));
    return d;
}
__device__ __forceinline__ float2 unpack2_(unsigned long long v) {
    float2 r;
    asm("mov.b64 {%0, %1}, %2;" : "=f"(r.x), "=f"(r.y) : "l"(v));
    return r;
}

// ============================================================================
// Phase 1: xproj[t,b, g*128 + j] = sum_i x[t,b,i] * Wg[i,j] + bg[j]
// Block tile = 64 rows x 128 cols (one gate), 256 threads, 4x8 reg tile,
// inner product packed as f32x2 over the c-dimension.
// ============================================================================
__global__ __launch_bounds__(256, 2) void xproj_kernel(
    const float* __restrict__ x,
    const float* __restrict__ Wir, const float* __restrict__ Wiz, const float* __restrict__ Win,
    const float* __restrict__ bir, const float* __restrict__ biz, const float* __restrict__ bin_)
{
    __shared__ __align__(16) float xs[I_SIZE][68];
    __shared__ __align__(16) float ws[I_SIZE][H_SIZE];
    __shared__ float bs[H_SIZE];

    const int g = blockIdx.y;
    const float* __restrict__ W    = (g == 0) ? Wir : (g == 1) ? Wiz : Win;
    const float* __restrict__ bias = (g == 0) ? bir : (g == 1) ? biz : bin_;

    const int tid = threadIdx.x;
    const size_t r_base = (size_t)blockIdx.x * 64;

    const float* __restrict__ xg = x + r_base * I_SIZE;
    #pragma unroll
    for (int s = 0; s < 16; s++) {
        int idx = tid + 256 * s;
        int row = idx >> 6;
        int i   = idx & 63;
        xs[i][row] = xg[idx];
    }
    #pragma unroll
    for (int s = 0; s < 32; s++) {
        int idx = tid + 256 * s;
        ((float*)ws)[idx] = W[idx];
    }
    if (tid < H_SIZE) bs[tid] = bias[tid];
    __syncthreads();

    const int tr = tid & 15;
    const int tc = tid >> 4;
    const int r0 = tr * 4;
    const int c0 = tc * 8;

    unsigned long long accp[4][4];
    #pragma unroll
    for (int r = 0; r < 4; r++)
        #pragma unroll
        for (int c = 0; c < 4; c++)
            accp[r][c] = 0ull;

    #pragma unroll 8
    for (int k = 0; k < I_SIZE; k++) {
        float4 xa = *(const float4*)&xs[k][r0];
        const ulonglong2* wrow = (const ulonglong2*)&ws[k][c0];
        ulonglong2 wp01 = wrow[0];
        ulonglong2 wp23 = wrow[1];
        unsigned long long xd[4] = {dup2_(xa.x), dup2_(xa.y), dup2_(xa.z), dup2_(xa.w)};
        #pragma unroll
        for (int r = 0; r < 4; r++) {
            accp[r][0] = fma2_(xd[r], wp01.x, accp[r][0]);
            accp[r][1] = fma2_(xd[r], wp01.y, accp[r][1]);
            accp[r][2] = fma2_(xd[r], wp23.x, accp[r][2]);
            accp[r][3] = fma2_(xd[r], wp23.y, accp[r][3]);
        }
    }

    #pragma unroll
    for (int r = 0; r < 4; r++) {
        size_t row = r_base + (size_t)(r0 + r);
        float* op = g_xproj + row * (3 * H_SIZE) + g * H_SIZE + c0;
        float2 p0 = unpack2_(accp[r][0]);
        float2 p1 = unpack2_(accp[r][1]);
        float2 p2 = unpack2_(accp[r][2]);
        float2 p3 = unpack2_(accp[r][3]);
        float4 o0, o1;
        o0.x = p0.x + bs[c0 + 0];
        o0.y = p0.y + bs[c0 + 1];
        o0.z = p1.x + bs[c0 + 2];
        o0.w = p1.y + bs[c0 + 3];
        o1.x = p2.x + bs[c0 + 4];
        o1.y = p2.y + bs[c0 + 5];
        o1.z = p3.x + bs[c0 + 6];
        o1.w = p3.y + bs[c0 + 7];
        *(float4*)(op)     = o0;
        *(float4*)(op + 4) = o1;
    }
}

// ============================================================================
// Phase 2: persistent per-batch GRU recurrence + fused classifier.
// grid = 128 blocks (2 batch rows each), 768 threads = 24 warps (6/SMSP).
// thread = (gate g, hidden col j, k-half kh): tid = g*256 + j*2 + kh.
// Each thread: 32 register f32x2 weight pairs (half a Wh column),
// 64 FFMA2 + 32 LDS.128 per step. k-half partials reduced by a single
// lane-pair shuffle (adjacent lanes share j) — no extra barrier.
// ============================================================================
__global__ __launch_bounds__(768, 1) void gru_kernel(
    const float* __restrict__ Whr, const float* __restrict__ Whz, const float* __restrict__ Whn,
    const float* __restrict__ bhn, const float* __restrict__ Wc,  const float* __restrict__ bc,
    float* __restrict__ out)
{
    __shared__ __align__(16) float h_s[2][H_SIZE];
    __shared__ float r_s[2][H_SIZE];
    __shared__ float z_s[2][H_SIZE];
    __shared__ float cls[2][8];

    const int tid  = threadIdx.x;
    const int g    = tid >> 8;         // 0=r, 1=z, 2=n
    const int rt   = tid & 255;
    const int j    = rt >> 1;          // 0..127
    const int kh   = rt & 1;           // k-half
    const int lane = tid & 31;
    const int b0   = blockIdx.x * 2;
    const int k0   = kh * 64;

    const float* __restrict__ Wh = (g == 0) ? Whr : (g == 1) ? Whz : Whn;

    // Register-resident half weight column, packed over k pairs.
    unsigned long long w2[32];
    #pragma unroll
    for (int m = 0; m < 32; m++)
        w2[m] = pack2_(Wh[(k0 + 2 * m) * H_SIZE + j],
                       Wh[(k0 + 2 * m + 1) * H_SIZE + j]);

    const float bhn_j = bhn[j];
    const float wc_j  = Wc[j];
    const float bc0   = bc[0];

    if (tid < 2 * H_SIZE) ((float*)h_s)[tid] = 0.0f;   // h0 = 0
    __syncthreads();

    const float* __restrict__ xp = g_xproj + (size_t)b0 * (3 * H_SIZE) + g * H_SIZE + j;
    const size_t step_stride = (size_t)B_SIZE * 3 * H_SIZE;

    const ulonglong2* __restrict__ h0q = (const ulonglong2*)&h_s[0][k0];
    const ulonglong2* __restrict__ h1q = (const ulonglong2*)&h_s[1][k0];

    for (int t = 0; t < T_STEPS; t++) {
        const float* xpt = xp + (size_t)t * step_stride;
        float x0 = xpt[0];
        float x1 = xpt[3 * H_SIZE];

        // Partial dot over this thread's 64 k-values, packed f32x2.
        unsigned long long a00 = 0ull, a01 = 0ull;
        unsigned long long a10 = 0ull, a11 = 0ull;
        #pragma unroll
        for (int m = 0; m < 16; m++) {
            ulonglong2 v0 = h0q[m];   // pairs (k0+4m,k0+4m+1),(k0+4m+2,k0+4m+3)
            ulonglong2 v1 = h1q[m];
            a00 = fma2_(v0.x, w2[2 * m + 0], a00);
            a01 = fma2_(v0.y, w2[2 * m + 1], a01);
            a10 = fma2_(v1.x, w2[2 * m + 0], a10);
            a11 = fma2_(v1.y, w2[2 * m + 1], a11);
        }
        float2 u0a = unpack2_(a00), u0b = unpack2_(a01);
        float2 u1a = unpack2_(a10), u1b = unpack2_(a11);
        float acc0 = (u0a.x + u0a.y) + (u0b.x + u0b.y);
        float acc1 = (u1a.x + u1a.y) + (u1b.x + u1b.y);

        // Combine k-halves: adjacent lanes (kh=0, kh=1) share the same j.
        acc0 += __shfl_down_sync(0xffffffffu, acc0, 1);
        acc1 += __shfl_down_sync(0xffffffffu, acc1, 1);
        // Valid on even lanes (kh == 0).

        if (kh == 0) {
            if (g == 0) {
                r_s[0][j] = sigmoidf_(x0 + acc0);
                r_s[1][j] = sigmoidf_(x1 + acc1);
            } else if (g == 1) {
                z_s[0][j] = sigmoidf_(x0 + acc0);
                z_s[1][j] = sigmoidf_(x1 + acc1);
            }
        }
        __syncthreads();   // r,z ready

        if (g == 2) {
            float v0 = 0.0f, v1 = 0.0f;
            if (kh == 0) {
                float h0o = h_s[0][j];
                float h1o = h_s[1][j];
                float n0 = tanhf_(x0 + r_s[0][j] * (acc0 + bhn_j));
                float n1 = tanhf_(x1 + r_s[1][j] * (acc1 + bhn_j));
                float z0 = z_s[0][j];
                float z1 = z_s[1][j];
                float hn0 = (1.0f - z0) * n0 + z0 * h0o;
                float hn1 = (1.0f - z1) * n1 + z1 * h1o;
                h_s[0][j] = hn0;
                h_s[1][j] = hn1;
                v0 = hn0 * wc_j;
                v1 = hn1 * wc_j;
            }
            // Fused classifier: warp covers 16 j's (even lanes hold values).
            #pragma unroll
            for (int off = 16; off > 0; off >>= 1) {
                v0 += __shfl_down_sync(0xffffffffu, v0, off);
                v1 += __shfl_down_sync(0xffffffffu, v1, off);
            }
            if (lane == 0) {
                int w8 = (tid >> 5) & 7;   // warp index within gate-2 group
                cls[0][w8] = v0;
                cls[1][w8] = v1;
            }
        }
        __syncthreads();   // h_new + cls ready

        if (tid < 2) {
            float s = ((cls[tid][0] + cls[tid][1]) + (cls[tid][2] + cls[tid][3]))
                    + ((cls[tid][4] + cls[tid][5]) + (cls[tid][6] + cls[tid][7])) + bc0;
            out[(size_t)t * B_SIZE + b0 + tid] = sigmoidf_(s);
        }
        // cls is re-read (tid<2) before gate-2 warps can rewrite it: the rewrite
        // is gated by the NEXT iteration's first __syncthreads, which requires
        // tid 0/1 to have arrived, i.e. after their read.
    }
}

// ============================================================================
extern "C" void kernel_launch(void* const* d_in, const int* in_sizes, int n_in,
                              void* d_out, int out_size)
{
    const float* x    = (const float*)d_in[0];
    const float* Wir  = (const float*)d_in[1];
    const float* Wiz  = (const float*)d_in[2];
    const float* Win  = (const float*)d_in[3];
    const float* bir  = (const float*)d_in[4];
    const float* biz  = (const float*)d_in[5];
    const float* bin_ = (const float*)d_in[6];
    const float* Whr  = (const float*)d_in[7];
    const float* Whz  = (const float*)d_in[8];
    const float* Whn  = (const float*)d_in[9];
    const float* bhn  = (const float*)d_in[10];
    const float* Wc   = (const float*)d_in[11];
    const float* bc   = (const float*)d_in[12];
    float* out = (float*)d_out;

    dim3 grid1((T_STEPS * B_SIZE) / 64, 3);
    xproj_kernel<<<grid1, 256>>>(x, Wir, Wiz, Win, bir, biz, bin_);

    gru_kernel<<<B_SIZE / 2, 768>>>(Whr, Whz, Whn, bhn, Wc, bc, out);
}

// round 10
// speedup vs baseline: 2.2419x; 2.2419x over previous
#include <cuda_runtime.h>
#include <cstdint>
#include <cstddef>

#define T_STEPS 2048
#define B_SIZE  256
#define I_SIZE  64
#define H_SIZE  128

// Scratch: input projections x@Wi + bi, layout [T][B][3*H] (805 MB)
__device__ float g_xproj[(size_t)T_STEPS * B_SIZE * 3 * H_SIZE];
// Scratch: hidden states hs [T][B][H] (268 MB) for deferred classifier
__device__ float g_hs[(size_t)T_STEPS * B_SIZE * H_SIZE];

__device__ __forceinline__ float sigmoidf_(float x) {
    return 1.0f / (1.0f + __expf(-x));
}
__device__ __forceinline__ float tanhf_(float x) {
    return 1.0f - 2.0f / (1.0f + __expf(2.0f * x));
}

// ---- packed f32x2 helpers (Blackwell FFMA2) --------------------------------
__device__ __forceinline__ unsigned long long fma2_(unsigned long long a,
                                                    unsigned long long b,
                                                    unsigned long long c) {
    unsigned long long d;
    asm("fma.rn.f32x2 %0, %1, %2, %3;" : "=l"(d) : "l"(a), "l"(b), "l"(c));
    return d;
}
__device__ __forceinline__ unsigned long long dup2_(float x) {
    unsigned long long d;
    asm("mov.b64 %0, {%1, %1};" : "=l"(d) : "f"(x));
    return d;
}
__device__ __forceinline__ float2 unpack2_(unsigned long long v) {
    float2 r;
    asm("mov.b64 {%0, %1}, %2;" : "=f"(r.x), "=f"(r.y) : "l"(v));
    return r;
}

// ============================================================================
// Phase 1: xproj[t,b, g*128 + j] = sum_i x[t,b,i] * Wg[i,j] + bg[j]
// Block tile = 64 rows x 128 cols (one gate), 128 threads, 4x16 register tile
// packed f32x2 over cols. Half-warp shares W addresses (broadcast LDS);
// x tile stored transposed with XOR swizzle to avoid bank conflicts.
// SMEM exactly 48KB: xs 16KB + ws 32KB.
// ============================================================================
// swizzled transposed x tile: element (i, row) at xs[i*64 + (row ^ (i & 60))]
#define XS_IDX(i, row) ((i) * 64 + ((row) ^ ((i) & 60)))

__global__ __launch_bounds__(128, 3) void xproj_kernel(
    const float* __restrict__ x,
    const float* __restrict__ Wir, const float* __restrict__ Wiz, const float* __restrict__ Win,
    const float* __restrict__ bir, const float* __restrict__ biz, const float* __restrict__ bin_)
{
    __shared__ __align__(16) float xs[I_SIZE * 64];       // 16384 B
    __shared__ __align__(16) float ws[I_SIZE * H_SIZE];   // 32768 B

    const int g = blockIdx.y;
    const float* __restrict__ W    = (g == 0) ? Wir : (g == 1) ? Wiz : Win;
    const float* __restrict__ bias = (g == 0) ? bir : (g == 1) ? biz : bin_;

    const int tid = threadIdx.x;
    const size_t r_base = (size_t)blockIdx.x * 64;

    // Load x tile [64 rows x 64 i] -> transposed+swizzled SMEM.
    const float4* __restrict__ xg4 = (const float4*)(x + r_base * I_SIZE);
    #pragma unroll
    for (int s = 0; s < 8; s++) {
        int idx4 = tid + 128 * s;            // 0..1023 float4s
        float4 v = xg4[idx4];
        int row = idx4 >> 4;                 // 16 float4 per row
        int i0  = (idx4 & 15) * 4;
        xs[XS_IDX(i0 + 0, row)] = v.x;
        xs[XS_IDX(i0 + 1, row)] = v.y;
        xs[XS_IDX(i0 + 2, row)] = v.z;
        xs[XS_IDX(i0 + 3, row)] = v.w;
    }
    // Load W [64 x 128] natural layout.
    const float4* __restrict__ Wg4 = (const float4*)W;
    #pragma unroll
    for (int s = 0; s < 16; s++) {
        int idx4 = tid + 128 * s;            // 0..2047
        ((float4*)ws)[idx4] = Wg4[idx4];
    }
    __syncthreads();

    const int tr = tid & 15;                 // 16 row-groups
    const int tc = tid >> 4;                 // 8 col-groups
    const int r0 = tr * 4;
    const int c0 = tc * 16;

    unsigned long long accp[4][8];
    #pragma unroll
    for (int r = 0; r < 4; r++)
        #pragma unroll
        for (int c = 0; c < 8; c++)
            accp[r][c] = 0ull;

    #pragma unroll 4
    for (int k = 0; k < I_SIZE; k++) {
        // rows r0..r0+3 contiguous in swizzled layout (swizzle flips bits >= 2)
        float4 xa = *(const float4*)&xs[XS_IDX(k, r0)];
        const ulonglong2* wr = (const ulonglong2*)&ws[k * H_SIZE + c0];
        ulonglong2 wq0 = wr[0], wq1 = wr[1], wq2 = wr[2], wq3 = wr[3];
        unsigned long long wp[8] = {wq0.x, wq0.y, wq1.x, wq1.y,
                                    wq2.x, wq2.y, wq3.x, wq3.y};
        unsigned long long xd[4] = {dup2_(xa.x), dup2_(xa.y), dup2_(xa.z), dup2_(xa.w)};
        #pragma unroll
        for (int r = 0; r < 4; r++)
            #pragma unroll
            for (int c = 0; c < 8; c++)
                accp[r][c] = fma2_(xd[r], wp[c], accp[r][c]);
    }

    // Bias (L1-cached global read, once per thread).
    const float4* __restrict__ bp = (const float4*)(bias + c0);
    float4 b0 = bp[0], b1 = bp[1], b2 = bp[2], b3 = bp[3];
    float bv[16] = {b0.x, b0.y, b0.z, b0.w, b1.x, b1.y, b1.z, b1.w,
                    b2.x, b2.y, b2.z, b2.w, b3.x, b3.y, b3.z, b3.w};

    #pragma unroll
    for (int r = 0; r < 4; r++) {
        size_t row = r_base + (size_t)(r0 + r);
        float* op = g_xproj + row * (3 * H_SIZE) + g * H_SIZE + c0;
        #pragma unroll
        for (int q = 0; q < 4; q++) {
            float2 pa = unpack2_(accp[r][2 * q + 0]);
            float2 pb = unpack2_(accp[r][2 * q + 1]);
            float4 o;
            o.x = pa.x + bv[4 * q + 0];
            o.y = pa.y + bv[4 * q + 1];
            o.z = pb.x + bv[4 * q + 2];
            o.w = pb.y + bv[4 * q + 3];
            *(float4*)(op + 4 * q) = o;
        }
    }
}

// ============================================================================
// Phase 2: persistent per-batch GRU recurrence (R7 dot structure).
// grid = 128 blocks (2 batch rows each), 384 threads, 167-ish regs.
// Epilogue parallelized: gate-2 thread updates row 0, gate-1 thread row 1.
// Classifier deferred to phase 3 (h written to g_hs).
// x(t+1) prefetched one full step ahead.
// ============================================================================
__global__ __launch_bounds__(384, 1) void gru_kernel(
    const float* __restrict__ Whr, const float* __restrict__ Whz, const float* __restrict__ Whn,
    const float* __restrict__ bhn)
{
    __shared__ __align__(16) float h_s[2][H_SIZE];
    __shared__ float r_s[2][H_SIZE];
    __shared__ float z0_s[H_SIZE];     // z row 0 (gate-1 keeps z1 in reg)
    __shared__ float a1_s[H_SIZE];     // n-dot row 1 (gate-2 keeps acc0)
    __shared__ float xn1_s[H_SIZE];    // xn row 1

    const int tid = threadIdx.x;
    const int g   = tid >> 7;       // 0=r, 1=z, 2=n
    const int j   = tid & 127;
    const int b0  = blockIdx.x * 2;

    const float* __restrict__ Wh = (g == 0) ? Whr : (g == 1) ? Whz : Whn;

    // Register-resident weight column: w[k] = Wh[k][j]
    float w[H_SIZE];
    #pragma unroll
    for (int k = 0; k < H_SIZE; k++) w[k] = Wh[k * H_SIZE + j];

    const float bhn_j = bhn[j];

    if (tid < 2 * H_SIZE) ((float*)h_s)[tid] = 0.0f;   // h0 = 0
    __syncthreads();

    const float* __restrict__ xp = g_xproj + (size_t)b0 * (3 * H_SIZE) + g * H_SIZE + j;
    const size_t step_stride = (size_t)B_SIZE * 3 * H_SIZE;

    // preload x for t = 0
    float x0 = xp[0];
    float x1 = xp[3 * H_SIZE];

    for (int t = 0; t < T_STEPS; t++) {
        // prefetch x for t+1 (hidden behind the dot below)
        float nx0 = 0.0f, nx1 = 0.0f;
        if (t + 1 < T_STEPS) {
            const float* xq = xp + (size_t)(t + 1) * step_stride;
            nx0 = xq[0];
            nx1 = xq[3 * H_SIZE];
        }

        // acc[row] = sum_k h[row][k] * Wh[k][j]
        float a0 = 0.f, a1 = 0.f, a2 = 0.f, a3 = 0.f;
        float d0 = 0.f, d1 = 0.f, d2 = 0.f, d3 = 0.f;
        #pragma unroll
        for (int k4 = 0; k4 < H_SIZE / 4; k4++) {
            float4 h0 = *(const float4*)&h_s[0][k4 * 4];
            float4 h1 = *(const float4*)&h_s[1][k4 * 4];
            a0 = fmaf(h0.x, w[4 * k4 + 0], a0);
            a1 = fmaf(h0.y, w[4 * k4 + 1], a1);
            a2 = fmaf(h0.z, w[4 * k4 + 2], a2);
            a3 = fmaf(h0.w, w[4 * k4 + 3], a3);
            d0 = fmaf(h1.x, w[4 * k4 + 0], d0);
            d1 = fmaf(h1.y, w[4 * k4 + 1], d1);
            d2 = fmaf(h1.z, w[4 * k4 + 2], d2);
            d3 = fmaf(h1.w, w[4 * k4 + 3], d3);
        }
        float acc0 = (a0 + a1) + (a2 + a3);
        float acc1 = (d0 + d1) + (d2 + d3);

        float z1r = 0.0f;                       // gate-1 keeps z row1 in reg
        if (g == 0) {
            r_s[0][j] = sigmoidf_(x0 + acc0);
            r_s[1][j] = sigmoidf_(x1 + acc1);
        } else if (g == 1) {
            z0_s[j] = sigmoidf_(x0 + acc0);
            z1r     = sigmoidf_(x1 + acc1);
        } else {
            a1_s[j]  = acc1;                    // raw n-dot row1
            xn1_s[j] = x1;                      // xn row1
        }
        __syncthreads();   // r, z0, a1, xn1 ready

        if (g == 2) {
            // row 0 update (acc0, x0 live in regs)
            float h0o = h_s[0][j];
            float n0  = tanhf_(x0 + r_s[0][j] * (acc0 + bhn_j));
            float z0  = z0_s[j];
            float hn0 = (1.0f - z0) * n0 + z0 * h0o;
            h_s[0][j] = hn0;
            g_hs[((size_t)t * B_SIZE + b0) * H_SIZE + j] = hn0;
        } else if (g == 1) {
            // row 1 update (z1 live in reg)
            float h1o = h_s[1][j];
            float n1  = tanhf_(xn1_s[j] + r_s[1][j] * (a1_s[j] + bhn_j));
            float hn1 = (1.0f - z1r) * n1 + z1r * h1o;
            h_s[1][j] = hn1;
            g_hs[((size_t)t * B_SIZE + b0 + 1) * H_SIZE + j] = hn1;
        }
        __syncthreads();   // h_new ready for next step's dot

        x0 = nx0;
        x1 = nx1;
    }
}

// ============================================================================
// Phase 3: classifier out[o] = sigmoid(dot(hs[o,:], Wc) + bc), o = t*B + b.
// Warp per output: lane loads one float4 of h and Wc, 5-level shuffle reduce.
// Memory-bound: 268 MB streamed.
// ============================================================================
__global__ __launch_bounds__(256) void cls_kernel(
    const float* __restrict__ Wc, const float* __restrict__ bc,
    float* __restrict__ out)
{
    const int lane = threadIdx.x & 31;
    const size_t o = (size_t)blockIdx.x * 8 + (threadIdx.x >> 5);

    float4 h4 = *(const float4*)&g_hs[o * H_SIZE + lane * 4];
    float4 w4 = *(const float4*)&Wc[lane * 4];
    float v = fmaf(h4.x, w4.x, fmaf(h4.y, w4.y, fmaf(h4.z, w4.z, h4.w * w4.w)));
    #pragma unroll
    for (int off = 16; off > 0; off >>= 1)
        v += __shfl_down_sync(0xffffffffu, v, off);
    if (lane == 0) out[o] = sigmoidf_(v + bc[0]);
}

// ============================================================================
extern "C" void kernel_launch(void* const* d_in, const int* in_sizes, int n_in,
                              void* d_out, int out_size)
{
    const float* x    = (const float*)d_in[0];
    const float* Wir  = (const float*)d_in[1];
    const float* Wiz  = (const float*)d_in[2];
    const float* Win  = (const float*)d_in[3];
    const float* bir  = (const float*)d_in[4];
    const float* biz  = (const float*)d_in[5];
    const float* bin_ = (const float*)d_in[6];
    const float* Whr  = (const float*)d_in[7];
    const float* Whz  = (const float*)d_in[8];
    const float* Whn  = (const float*)d_in[9];
    const float* bhn  = (const float*)d_in[10];
    const float* Wc   = (const float*)d_in[11];
    const float* bc   = (const float*)d_in[12];
    float* out = (float*)d_out;

    // Phase 1: input projections (fully parallel over T*B).
    dim3 grid1((T_STEPS * B_SIZE) / 64, 3);
    xproj_kernel<<<grid1, 128>>>(x, Wir, Wiz, Win, bir, biz, bin_);

    // Phase 2: sequential recurrence, batch-parallel across 128 blocks.
    gru_kernel<<<B_SIZE / 2, 384>>>(Whr, Whz, Whn, bhn);

    // Phase 3: classifier over all T*B hidden states.
    cls_kernel<<<(T_STEPS * B_SIZE) / 8, 256>>>(Wc, bc, out);
}